// round 3
// baseline (speedup 1.0000x reference)
#include <cuda_runtime.h>

// Problem constants (fixed by the dataset)
namespace cfg {
constexpr int V = 17;      // nodes
constexpr int D = 128;     // feature dim
constexpr int H = 256;     // hidden dim
constexpr int E = 32;      // edges
constexpr float LN_EPS = 1e-5f;
constexpr int PAD = 20;    // padded row (floats) for 16B-aligned vector LDS

// shared-memory layout (float offsets)
constexpr int HT_OFF = 0;                 // hT[128][20]  h transposed
constexpr int P_OFF  = HT_OFF + D * PAD;  // P[17][256]
constexpr int Q_OFF  = P_OFF + V * H;     // Q[17][256]
constexpr int HS_OFF = Q_OFF + V * H;     // hsum[17][256]
constexpr int AG_OFF = HS_OFF + V * H;    // aggT[128][20]
constexpr int H2_OFF = AG_OFF + D * PAD;  // hid2T[256][20]
constexpr int SX_OFF = H2_OFF + H * PAD;  // xy.x [17]
constexpr int SY_OFF = SX_OFF + V;        // xy.y [17]
constexpr int MF_OFF = SY_OFF + V;        // mask float [17]
constexpr int IV_OFF = MF_OFF + V;        // 1/max(denom,1) [17]
constexpr int HB_OFF = IV_OFF + V;        // has_neighbors [17]
constexpr int DN_OFF = HB_OFF + V;        // denom [17]
constexpr int RX_OFF = DN_OFF + V;        // rel x [32]
constexpr int RY_OFF = RX_OFF + E;        // rel y [32]
constexpr int VA_OFF = RY_OFF + E;        // edge_valid [32]
constexpr int DS_OFF = VA_OFF + E;        // int dst[32], src[32]
constexpr int SMEM_FLOATS = DS_OFF + 2 * E;
constexpr int SMEM_BYTES = SMEM_FLOATS * 4;

// aliases (regions free by the time these are used)
constexpr int RED_OFF = P_OFF;  // reduction buffer [128][17]
constexpr int XB_OFF  = Q_OFF;  // x buffer [17][128]
}  // namespace cfg

__device__ __forceinline__ void load17(const float* __restrict__ p, float* a) {
    // p is 16B-aligned (rows padded to 20 floats). Broadcast LDS.128 x4 + scalar.
    float4 t0 = *reinterpret_cast<const float4*>(p);
    float4 t1 = *reinterpret_cast<const float4*>(p + 4);
    float4 t2 = *reinterpret_cast<const float4*>(p + 8);
    float4 t3 = *reinterpret_cast<const float4*>(p + 12);
    a[0] = t0.x; a[1] = t0.y; a[2] = t0.z; a[3] = t0.w;
    a[4] = t1.x; a[5] = t1.y; a[6] = t1.z; a[7] = t1.w;
    a[8] = t2.x; a[9] = t2.y; a[10] = t2.z; a[11] = t2.w;
    a[12] = t3.x; a[13] = t3.y; a[14] = t3.z; a[15] = t3.w;
    a[16] = p[16];
}

__global__ __launch_bounds__(256, 2) void graph_layer_kernel(
    const float* __restrict__ h, const float* __restrict__ xy,
    const void* __restrict__ jmask_raw, const void* __restrict__ edge_raw,
    const float* __restrict__ ew1, const float* __restrict__ eb1,
    const float* __restrict__ ew2, const float* __restrict__ eb2,
    const float* __restrict__ nw1, const float* __restrict__ nb1,
    const float* __restrict__ nw2, const float* __restrict__ nb2,
    const float* __restrict__ gamma, const float* __restrict__ beta,
    float* __restrict__ out)
{
    using namespace cfg;
    extern __shared__ float sm[];
    int* smi = reinterpret_cast<int*>(sm + DS_OFF);  // [dst[32] | src[32]]
    __shared__ int s_etype;  // 0 = int32, 1 = int64
    __shared__ int s_mtype;  // 0 = bool(u8), 1 = int32, 2 = float32

    const int n = blockIdx.x;
    const int tid = threadIdx.x;
    const long long nbase = (long long)n * V;

    // ---------------- Phase A0: dtype self-detection ----------------
    if (tid == 0) {
        // edge_index: int32 vs int64. In int64 layout (values < 17) all odd
        // 32-bit words are 0; in int32 layout odd words are src values
        // (all-zero probability ~17^-32).
        const unsigned* ew = (const unsigned*)edge_raw;
        unsigned odd_or = 0;
        #pragma unroll
        for (int i = 1; i < 2 * E; i += 2) odd_or |= ew[i];
        s_etype = (odd_or == 0) ? 1 : 0;

        // joint_mask: sample 64 words. all in {0,1} -> int32;
        // all in {0, 0x3F800000} -> float32; else packed bool bytes.
        const unsigned* mw = (const unsigned*)jmask_raw;
        bool all_i = true, all_f = true;
        #pragma unroll
        for (int i = 0; i < 64; i++) {
            unsigned w = mw[i];
            all_i = all_i && (w <= 1u);
            all_f = all_f && (w == 0u || w == 0x3F800000u);
        }
        s_mtype = all_i ? 1 : (all_f ? 2 : 0);
    }
    __syncthreads();

    // ---------------- Phase A: loads ----------------
    for (int idx = tid; idx < V * D; idx += 256) {
        int v = idx / D, k = idx % D;
        sm[HT_OFF + k * PAD + v] = h[(nbase + v) * D + k];
    }
    if (tid < V) {
        sm[SX_OFF + tid] = xy[(nbase + tid) * 2 + 0];
        sm[SY_OFF + tid] = xy[(nbase + tid) * 2 + 1];
        float mf;
        if (s_mtype == 0)
            mf = ((const unsigned char*)jmask_raw)[nbase + tid] ? 1.0f : 0.0f;
        else if (s_mtype == 1)
            mf = ((const int*)jmask_raw)[nbase + tid] ? 1.0f : 0.0f;
        else
            mf = (((const float*)jmask_raw)[nbase + tid] != 0.0f) ? 1.0f : 0.0f;
        sm[MF_OFF + tid] = mf;
    }
    if (tid < E) {
        int dv, sv;
        if (s_etype == 1) {
            const long long* e64 = (const long long*)edge_raw;
            dv = (int)e64[tid * 2 + 0];
            sv = (int)e64[tid * 2 + 1];
        } else {
            const int* e32 = (const int*)edge_raw;
            dv = e32[tid * 2 + 0];
            sv = e32[tid * 2 + 1];
        }
        smi[tid]     = dv;
        smi[E + tid] = sv;
    }
    __syncthreads();
    if (tid < E) {
        int dv = smi[tid], sv = smi[E + tid];
        sm[RX_OFF + tid] = sm[SX_OFF + sv] - sm[SX_OFF + dv];
        sm[RY_OFF + tid] = sm[SY_OFF + sv] - sm[SY_OFF + dv];
        sm[VA_OFF + tid] = sm[MF_OFF + dv] * sm[MF_OFF + sv];
    }
    __syncthreads();
    if (tid < V) {
        float dn = 0.0f;
        #pragma unroll
        for (int e = 0; e < E; e++)
            if (smi[e] == tid) dn += sm[VA_OFF + e];
        sm[DN_OFF + tid] = dn;
        sm[IV_OFF + tid] = 1.0f / fmaxf(dn, 1.0f);
        sm[HB_OFF + tid] = dn > 0.0f ? 1.0f : 0.0f;
    }
    __syncthreads();

    // ---------------- Phase B: P = h @ ew1[0:128], Q = h @ ew1[128:256] ----------------
    {
        const int c = tid * 2;  // combined column 0..510 (0..255 -> P, 256..511 -> Q)
        const float* wp = (c < H) ? (ew1 + c) : (ew1 + D * H + (c - H));
        float acc0[V], acc1[V];
        #pragma unroll
        for (int v = 0; v < V; v++) { acc0[v] = 0.f; acc1[v] = 0.f; }
        #pragma unroll 4
        for (int k = 0; k < D; k++) {
            float a[V];
            load17(sm + HT_OFF + k * PAD, a);
            float2 w = *reinterpret_cast<const float2*>(wp + (long long)k * H);
            #pragma unroll
            for (int v = 0; v < V; v++) {
                acc0[v] = fmaf(a[v], w.x, acc0[v]);
                acc1[v] = fmaf(a[v], w.y, acc1[v]);
            }
        }
        float* dbuf = (c < H) ? (sm + P_OFF) : (sm + Q_OFF);
        const int cc = c & (H - 1);
        #pragma unroll
        for (int v = 0; v < V; v++) {
            dbuf[v * H + cc]     = acc0[v];
            dbuf[v * H + cc + 1] = acc1[v];
        }
    }
    __syncthreads();

    // ---------------- Phase C: hsum[v][j] = sum_{e:dst=v} valid_e*relu(P[dst]+Q[src]+rel.w+b1) ----------------
    {
        const int j = tid;
        const float b1 = eb1[j];
        const float wx = ew1[(2 * D) * H + j];
        const float wy = ew1[(2 * D + 1) * H + j];
        #pragma unroll
        for (int v = 0; v < V; v++) sm[HS_OFF + v * H + j] = 0.0f;
        #pragma unroll
        for (int e = 0; e < E; e++) {
            int dv = smi[e], sv = smi[E + e];
            float hid = sm[P_OFF + dv * H + j] + sm[Q_OFF + sv * H + j]
                      + sm[RX_OFF + e] * wx + sm[RY_OFF + e] * wy + b1;
            hid = fmaxf(hid, 0.0f) * sm[VA_OFF + e];
            sm[HS_OFF + dv * H + j] += hid;
        }
    }
    __syncthreads();

    // ---------------- Phase C2: agg = (hsum @ ew2 + denom*eb2) / max(denom,1) ----------------
    {
        const int j = tid & (D - 1);
        const int kh = tid >> 7;  // split-K halves
        float acc[V];
        #pragma unroll
        for (int v = 0; v < V; v++) acc[v] = 0.0f;
        const float* w = ew2 + j;
        const int k0 = kh * 128;
        #pragma unroll 4
        for (int k = k0; k < k0 + 128; k++) {
            float wv = w[(long long)k * D];
            #pragma unroll
            for (int v = 0; v < V; v++)
                acc[v] = fmaf(sm[HS_OFF + v * H + k], wv, acc[v]);
        }
        if (kh) {
            #pragma unroll
            for (int v = 0; v < V; v++) sm[RED_OFF + j * V + v] = acc[v];
        }
        __syncthreads();
        if (!kh) {
            const float b2 = eb2[j];
            #pragma unroll
            for (int v = 0; v < V; v++) {
                float a = acc[v] + sm[RED_OFF + j * V + v] + sm[DN_OFF + v] * b2;
                sm[AG_OFF + j * PAD + v] = a * sm[IV_OFF + v];
            }
        }
    }
    __syncthreads();

    // ---------------- Phase D: hid2 = relu([h, agg] @ nw1 + nb1) ----------------
    {
        const int j = tid;
        float acc[V];
        #pragma unroll
        for (int v = 0; v < V; v++) acc[v] = 0.0f;
        const float* w = nw1 + j;
        #pragma unroll 4
        for (int k = 0; k < D; k++) {
            float a[V];
            load17(sm + HT_OFF + k * PAD, a);
            float wv = w[(long long)k * H];
            #pragma unroll
            for (int v = 0; v < V; v++) acc[v] = fmaf(a[v], wv, acc[v]);
        }
        #pragma unroll 4
        for (int k = 0; k < D; k++) {
            float a[V];
            load17(sm + AG_OFF + k * PAD, a);
            float wv = w[(long long)(D + k) * H];
            #pragma unroll
            for (int v = 0; v < V; v++) acc[v] = fmaf(a[v], wv, acc[v]);
        }
        const float b = nb1[j];
        #pragma unroll
        for (int v = 0; v < V; v++)
            sm[H2_OFF + j * PAD + v] = fmaxf(acc[v] + b, 0.0f);
    }
    __syncthreads();

    // ---------------- Phase E: delta = hid2 @ nw2 + nb2 ; x = h + delta*has ----------------
    {
        const int j = tid & (D - 1);
        const int kh = tid >> 7;
        float acc[V];
        #pragma unroll
        for (int v = 0; v < V; v++) acc[v] = 0.0f;
        const float* w = nw2 + j;
        const int k0 = kh * 128;
        #pragma unroll 4
        for (int k = k0; k < k0 + 128; k++) {
            float a[V];
            load17(sm + H2_OFF + k * PAD, a);
            float wv = w[(long long)k * D];
            #pragma unroll
            for (int v = 0; v < V; v++) acc[v] = fmaf(a[v], wv, acc[v]);
        }
        if (kh) {
            #pragma unroll
            for (int v = 0; v < V; v++) sm[RED_OFF + j * V + v] = acc[v];
        }
        __syncthreads();
        if (!kh) {
            const float b2 = nb2[j];
            #pragma unroll
            for (int v = 0; v < V; v++) {
                float delta = acc[v] + sm[RED_OFF + j * V + v] + b2;
                float xv = sm[HT_OFF + j * PAD + v] + delta * sm[HB_OFF + v];
                sm[XB_OFF + v * D + j] = xv;
            }
        }
    }
    __syncthreads();

    // ---------------- Phase F: LayerNorm + gamma/beta + mask ----------------
    {
        const int wrp = tid >> 5, lane = tid & 31;
        const float g0 = gamma[lane], g1 = gamma[lane + 32],
                    g2 = gamma[lane + 64], g3 = gamma[lane + 96];
        const float b0 = beta[lane], b1 = beta[lane + 32],
                    b2 = beta[lane + 64], b3 = beta[lane + 96];
        for (int v = wrp; v < V; v += 8) {
            float x0 = sm[XB_OFF + v * D + lane];
            float x1 = sm[XB_OFF + v * D + lane + 32];
            float x2 = sm[XB_OFF + v * D + lane + 64];
            float x3 = sm[XB_OFF + v * D + lane + 96];
            float s = x0 + x1 + x2 + x3;
            #pragma unroll
            for (int off = 16; off > 0; off >>= 1)
                s += __shfl_xor_sync(0xffffffffu, s, off);
            float mu = s * (1.0f / 128.0f);
            float d0 = x0 - mu, d1 = x1 - mu, d2 = x2 - mu, d3 = x3 - mu;
            float q = d0 * d0 + d1 * d1 + d2 * d2 + d3 * d3;
            #pragma unroll
            for (int off = 16; off > 0; off >>= 1)
                q += __shfl_xor_sync(0xffffffffu, q, off);
            float rstd = rsqrtf(q * (1.0f / 128.0f) + LN_EPS);
            float m = sm[MF_OFF + v];
            long long base = (nbase + v) * D;
            out[base + lane]      = (d0 * rstd * g0 + b0) * m;
            out[base + lane + 32] = (d1 * rstd * g1 + b1) * m;
            out[base + lane + 64] = (d2 * rstd * g2 + b2) * m;
            out[base + lane + 96] = (d3 * rstd * g3 + b3) * m;
        }
    }
}

extern "C" void kernel_launch(void* const* d_in, const int* in_sizes, int n_in,
                              void* d_out, int out_size) {
    using namespace cfg;
    const float* h = (const float*)d_in[0];
    const float* xy = (const float*)d_in[1];
    const void* jmask = d_in[2];
    const void* edge = d_in[3];
    const float* ew1 = (const float*)d_in[4];
    const float* eb1 = (const float*)d_in[5];
    const float* ew2 = (const float*)d_in[6];
    const float* eb2 = (const float*)d_in[7];
    const float* nw1 = (const float*)d_in[8];
    const float* nb1 = (const float*)d_in[9];
    const float* nw2 = (const float*)d_in[10];
    const float* nb2 = (const float*)d_in[11];
    const float* gamma = (const float*)d_in[12];
    const float* beta = (const float*)d_in[13];
    float* out = (float*)d_out;

    const int nbatch = in_sizes[0] / (V * D);

    cudaFuncSetAttribute(graph_layer_kernel,
                         cudaFuncAttributeMaxDynamicSharedMemorySize, SMEM_BYTES);
    graph_layer_kernel<<<nbatch, 256, SMEM_BYTES>>>(
        h, xy, jmask, edge, ew1, eb1, ew2, eb2,
        nw1, nb1, nw2, nb2, gamma, beta, out);
}

// round 4
// speedup vs baseline: 1.1816x; 1.1816x over previous
#include <cuda_runtime.h>

// Problem constants (fixed by the dataset)
namespace cfg {
constexpr int V = 17;      // nodes
constexpr int D = 128;     // feature dim
constexpr int H = 256;     // hidden dim
constexpr int E = 32;      // edges
constexpr float LN_EPS = 1e-5f;
constexpr int PAD = 20;    // padded row (floats), 80B => 16B-aligned rows

// ---- shared-memory layout (float offsets) ----
constexpr int HT_OFF  = 0;                   // hT[128][20], live A..E
constexpr int R3_OFF  = HT_OFF + D * PAD;    // 5120: hsumT[256][20] (C..C2), then hid2T[256][20] (D..E)
constexpr int HST_OFF = R3_OFF;
constexpr int H2T_OFF = R3_OFF;
constexpr int R2_OFF  = R3_OFF + H * PAD;    // 9088: P+Q (B..C), then AG+RED+XB
constexpr int P_OFF   = R2_OFF;              // P[17][256]
constexpr int Q_OFF   = R2_OFF + V * H;      // Q[17][256]
constexpr int AG_OFF  = R2_OFF;              // aggT[128][20] (C2..D)
constexpr int RED_OFF = R2_OFF + D * PAD;    // partials [256][17] (C2,D,E)
constexpr int XB_OFF  = RED_OFF + H * V;     // x[17][128] (E..F)
constexpr int R2_END  = XB_OFF + V * D;

constexpr int SX_OFF = R2_END;          // xy.x [17]
constexpr int SY_OFF = SX_OFF + V;      // xy.y [17]
constexpr int MF_OFF = SY_OFF + V;      // mask float [17]
constexpr int IV_OFF = MF_OFF + V;      // 1/max(denom,1) [17]
constexpr int HB_OFF = IV_OFF + V;      // has_neighbors [17]
constexpr int DN_OFF = HB_OFF + V;      // denom [17]
constexpr int RX_OFF = DN_OFF + V;      // rel x [32]
constexpr int RY_OFF = RX_OFF + E;      // rel y [32]
constexpr int VA_OFF = RY_OFF + E;      // edge_valid [32]
constexpr int SRX_OFF = VA_OFF + E;     // sorted rel x [32]
constexpr int SRY_OFF = SRX_OFF + E;    // sorted rel y [32]
constexpr int SVA_OFF = SRY_OFF + E;    // sorted valid [32]
constexpr int INT_OFF = SVA_OFF + E;    // int region
// ints: dst[32] src[32] ssrc[32] eord[32] cnt[17] off[18]
constexpr int I_DST = 0, I_SRC = 32, I_SSRC = 64, I_EORD = 96, I_CNT = 128, I_OFFA = 145;
constexpr int SMEM_FLOATS = INT_OFF + 163 + 13;  // pad
constexpr int SMEM_BYTES = SMEM_FLOATS * 4;
}  // namespace cfg

__device__ __forceinline__ void load17(const float* __restrict__ p, float* a) {
    float4 t0 = *reinterpret_cast<const float4*>(p);
    float4 t1 = *reinterpret_cast<const float4*>(p + 4);
    float4 t2 = *reinterpret_cast<const float4*>(p + 8);
    float4 t3 = *reinterpret_cast<const float4*>(p + 12);
    a[0] = t0.x; a[1] = t0.y; a[2] = t0.z; a[3] = t0.w;
    a[4] = t1.x; a[5] = t1.y; a[6] = t1.z; a[7] = t1.w;
    a[8] = t2.x; a[9] = t2.y; a[10] = t2.z; a[11] = t2.w;
    a[12] = t3.x; a[13] = t3.y; a[14] = t3.z; a[15] = t3.w;
    a[16] = p[16];
}

__global__ __launch_bounds__(256, 3) void graph_layer_kernel(
    const float* __restrict__ h, const float* __restrict__ xy,
    const void* __restrict__ jmask_raw, const void* __restrict__ edge_raw,
    const float* __restrict__ ew1, const float* __restrict__ eb1,
    const float* __restrict__ ew2, const float* __restrict__ eb2,
    const float* __restrict__ nw1, const float* __restrict__ nb1,
    const float* __restrict__ nw2, const float* __restrict__ nb2,
    const float* __restrict__ gamma, const float* __restrict__ beta,
    float* __restrict__ out)
{
    using namespace cfg;
    extern __shared__ float sm[];
    int* smi = reinterpret_cast<int*>(sm + INT_OFF);
    __shared__ int s_etype;  // 0 = int32, 1 = int64
    __shared__ int s_mtype;  // 0 = bool(u8), 1 = int32, 2 = float32

    const int n = blockIdx.x;
    const int tid = threadIdx.x;
    const long long nbase = (long long)n * V;

    // ---------------- Phase A0: dtype self-detection ----------------
    if (tid == 0) {
        const unsigned* ew = (const unsigned*)edge_raw;
        unsigned odd_or = 0;
        #pragma unroll
        for (int i = 1; i < 2 * E; i += 2) odd_or |= ew[i];
        s_etype = (odd_or == 0) ? 1 : 0;
        const unsigned* mw = (const unsigned*)jmask_raw;
        bool all_i = true, all_f = true;
        #pragma unroll
        for (int i = 0; i < 64; i++) {
            unsigned w = mw[i];
            all_i = all_i && (w <= 1u);
            all_f = all_f && (w == 0u || w == 0x3F800000u);
        }
        s_mtype = all_i ? 1 : (all_f ? 2 : 0);
    }
    // h transpose load (vectorized; independent of detection)
    {
        const float4* h4 = reinterpret_cast<const float4*>(h + nbase * D);
        for (int idx = tid; idx < V * D / 4; idx += 256) {
            int v = (idx * 4) / D, k4 = (idx * 4) % D;
            float4 t = h4[idx];
            sm[HT_OFF + (k4 + 0) * PAD + v] = t.x;
            sm[HT_OFF + (k4 + 1) * PAD + v] = t.y;
            sm[HT_OFF + (k4 + 2) * PAD + v] = t.z;
            sm[HT_OFF + (k4 + 3) * PAD + v] = t.w;
        }
    }
    if (tid < V) {
        sm[SX_OFF + tid] = xy[(nbase + tid) * 2 + 0];
        sm[SY_OFF + tid] = xy[(nbase + tid) * 2 + 1];
    }
    __syncthreads();

    if (tid < V) {
        float mf;
        if (s_mtype == 0)
            mf = ((const unsigned char*)jmask_raw)[nbase + tid] ? 1.0f : 0.0f;
        else if (s_mtype == 1)
            mf = ((const int*)jmask_raw)[nbase + tid] ? 1.0f : 0.0f;
        else
            mf = (((const float*)jmask_raw)[nbase + tid] != 0.0f) ? 1.0f : 0.0f;
        sm[MF_OFF + tid] = mf;
    }
    if (tid < E) {
        int dv, sv;
        if (s_etype == 1) {
            const long long* e64 = (const long long*)edge_raw;
            dv = (int)e64[tid * 2 + 0];
            sv = (int)e64[tid * 2 + 1];
        } else {
            const int* e32 = (const int*)edge_raw;
            dv = e32[tid * 2 + 0];
            sv = e32[tid * 2 + 1];
        }
        smi[I_DST + tid] = dv;
        smi[I_SRC + tid] = sv;
    }
    __syncthreads();

    if (tid < E) {
        int dv = smi[I_DST + tid], sv = smi[I_SRC + tid];
        sm[RX_OFF + tid] = sm[SX_OFF + sv] - sm[SX_OFF + dv];
        sm[RY_OFF + tid] = sm[SY_OFF + sv] - sm[SY_OFF + dv];
        sm[VA_OFF + tid] = sm[MF_OFF + dv] * sm[MF_OFF + sv];
    }
    if (tid >= 64 && tid < 64 + V) {
        int v = tid - 64, c = 0;
        #pragma unroll
        for (int e = 0; e < E; e++) c += (smi[I_DST + e] == v);
        smi[I_CNT + v] = c;
    }
    __syncthreads();

    if (tid == 0) {
        int o = 0;
        #pragma unroll
        for (int v = 0; v < V; v++) { smi[I_OFFA + v] = o; o += smi[I_CNT + v]; }
        smi[I_OFFA + V] = o;
    }
    __syncthreads();

    if (tid < V) {
        int pos = smi[I_OFFA + tid];
        float dn = 0.0f;
        #pragma unroll
        for (int e = 0; e < E; e++) {
            if (smi[I_DST + e] == tid) {
                smi[I_EORD + pos++] = e;
                dn += sm[VA_OFF + e];
            }
        }
        sm[DN_OFF + tid] = dn;
        sm[IV_OFF + tid] = 1.0f / fmaxf(dn, 1.0f);
        sm[HB_OFF + tid] = dn > 0.0f ? 1.0f : 0.0f;
    }
    __syncthreads();

    if (tid < E) {
        int e = smi[I_EORD + tid];
        smi[I_SSRC + tid] = smi[I_SRC + e];
        sm[SRX_OFF + tid] = sm[RX_OFF + e];
        sm[SRY_OFF + tid] = sm[RY_OFF + e];
        sm[SVA_OFF + tid] = sm[VA_OFF + e];
    }
    __syncthreads();

    // ------- Phase B: P = h @ ew1[0:128], Q = h @ ew1[128:256], 2 cols/thread -------
    {
        const int c = tid * 2;
        const float* wp = (c < H) ? (ew1 + c) : (ew1 + D * H + (c - H));
        float acc0[V], acc1[V];
        #pragma unroll
        for (int v = 0; v < V; v++) { acc0[v] = 0.f; acc1[v] = 0.f; }
        #pragma unroll 2
        for (int k = 0; k < D; k++) {
            float a[V];
            load17(sm + HT_OFF + k * PAD, a);
            float2 w = *reinterpret_cast<const float2*>(wp + (long long)k * H);
            #pragma unroll
            for (int v = 0; v < V; v++) {
                acc0[v] = fmaf(a[v], w.x, acc0[v]);
                acc1[v] = fmaf(a[v], w.y, acc1[v]);
            }
        }
        float* dbuf = (c < H) ? (sm + P_OFF) : (sm + Q_OFF);
        const int cc = c & (H - 1);
        #pragma unroll
        for (int v = 0; v < V; v++) {
            dbuf[v * H + cc]     = acc0[v];
            dbuf[v * H + cc + 1] = acc1[v];
        }
    }
    __syncthreads();

    // ------- Phase C: hsumT[j][v] = sum over edges of dst v (sorted lists) -------
    {
        const int j = tid;
        const float b1v = eb1[j];
        const float wx = ew1[(2 * D) * H + j];
        const float wy = ew1[(2 * D + 1) * H + j];
        int o0 = smi[I_OFFA + 0];
        #pragma unroll 1
        for (int v = 0; v < V; v++) {
            const int o1 = smi[I_OFFA + v + 1];
            const float pv = sm[P_OFF + v * H + j];
            float acc = 0.0f;
            for (int i = o0; i < o1; i++) {
                const int sv = smi[I_SSRC + i];
                float hid = pv + sm[Q_OFF + sv * H + j]
                          + sm[SRX_OFF + i] * wx + sm[SRY_OFF + i] * wy + b1v;
                acc = fmaf(fmaxf(hid, 0.0f), sm[SVA_OFF + i], acc);
            }
            sm[HST_OFF + j * PAD + v] = acc;
            o0 = o1;
        }
    }
    __syncthreads();

    // ------- Phase C2: agg = (hsumT^T @ ew2 + denom*eb2) / max(denom,1), split-K 2 -------
    {
        const int j = tid & (D - 1);
        const int kh = tid >> 7;
        float acc[V];
        #pragma unroll
        for (int v = 0; v < V; v++) acc[v] = 0.0f;
        const float* hb = sm + HST_OFF + kh * 128 * PAD;
        const float* w = ew2 + (long long)(kh * 128) * D + j;
        #pragma unroll 4
        for (int k = 0; k < 128; k++) {
            float a[V];
            load17(hb + k * PAD, a);
            float wv = w[(long long)k * D];
            #pragma unroll
            for (int v = 0; v < V; v++) acc[v] = fmaf(a[v], wv, acc[v]);
        }
        if (kh) {
            #pragma unroll
            for (int v = 0; v < V; v++) sm[RED_OFF + j * V + v] = acc[v];
        }
        __syncthreads();
        if (!kh) {
            const float b2 = eb2[j];
            #pragma unroll
            for (int v = 0; v < V; v++) {
                float a = acc[v] + sm[RED_OFF + j * V + v] + sm[DN_OFF + v] * b2;
                sm[AG_OFF + j * PAD + v] = a * sm[IV_OFF + v];
            }
        }
    }
    __syncthreads();

    // ------- Phase D: hid2 = relu([h, agg] @ nw1 + nb1), 2 cols/thread, split-K by source -------
    {
        const int c = (tid & 127) * 2;
        const int kh = tid >> 7;          // kh=0: h rows 0..127; kh=1: agg rows 128..255
        float acc0[V], acc1[V];
        #pragma unroll
        for (int v = 0; v < V; v++) { acc0[v] = 0.f; acc1[v] = 0.f; }
        const float* ab = sm + (kh ? AG_OFF : HT_OFF);
        const float* w = nw1 + (long long)(kh * 128) * H + c;
        #pragma unroll 2
        for (int k = 0; k < 128; k++) {
            float a[V];
            load17(ab + k * PAD, a);
            float2 wv = *reinterpret_cast<const float2*>(w + (long long)k * H);
            #pragma unroll
            for (int v = 0; v < V; v++) {
                acc0[v] = fmaf(a[v], wv.x, acc0[v]);
                acc1[v] = fmaf(a[v], wv.y, acc1[v]);
            }
        }
        if (kh) {
            #pragma unroll
            for (int v = 0; v < V; v++) {
                sm[RED_OFF + c * V + v]       = acc0[v];
                sm[RED_OFF + (c + 1) * V + v] = acc1[v];
            }
        }
        __syncthreads();
        if (!kh) {
            const float bb0 = nb1[c], bb1 = nb1[c + 1];
            #pragma unroll
            for (int v = 0; v < V; v++) {
                float h0 = fmaxf(acc0[v] + sm[RED_OFF + c * V + v] + bb0, 0.0f);
                float h1 = fmaxf(acc1[v] + sm[RED_OFF + (c + 1) * V + v] + bb1, 0.0f);
                sm[H2T_OFF + c * PAD + v]       = h0;
                sm[H2T_OFF + (c + 1) * PAD + v] = h1;
            }
        }
    }
    __syncthreads();

    // ------- Phase E: delta = hid2 @ nw2 + nb2 ; x = h + delta*has, split-K 2 -------
    {
        const int j = tid & (D - 1);
        const int kh = tid >> 7;
        float acc[V];
        #pragma unroll
        for (int v = 0; v < V; v++) acc[v] = 0.0f;
        const float* hb = sm + H2T_OFF + kh * 128 * PAD;
        const float* w = nw2 + (long long)(kh * 128) * D + j;
        #pragma unroll 4
        for (int k = 0; k < 128; k++) {
            float a[V];
            load17(hb + k * PAD, a);
            float wv = w[(long long)k * D];
            #pragma unroll
            for (int v = 0; v < V; v++) acc[v] = fmaf(a[v], wv, acc[v]);
        }
        if (kh) {
            #pragma unroll
            for (int v = 0; v < V; v++) sm[RED_OFF + j * V + v] = acc[v];
        }
        __syncthreads();
        if (!kh) {
            const float b2 = nb2[j];
            #pragma unroll
            for (int v = 0; v < V; v++) {
                float delta = acc[v] + sm[RED_OFF + j * V + v] + b2;
                float xv = sm[HT_OFF + j * PAD + v] + delta * sm[HB_OFF + v];
                sm[XB_OFF + v * D + j] = xv;
            }
        }
    }
    __syncthreads();

    // ------- Phase F: LayerNorm + gamma/beta + mask -------
    {
        const int wrp = tid >> 5, lane = tid & 31;
        const float g0 = gamma[lane], g1 = gamma[lane + 32],
                    g2 = gamma[lane + 64], g3 = gamma[lane + 96];
        const float b0 = beta[lane], b1 = beta[lane + 32],
                    b2 = beta[lane + 64], b3 = beta[lane + 96];
        for (int v = wrp; v < V; v += 8) {
            float x0 = sm[XB_OFF + v * D + lane];
            float x1 = sm[XB_OFF + v * D + lane + 32];
            float x2 = sm[XB_OFF + v * D + lane + 64];
            float x3 = sm[XB_OFF + v * D + lane + 96];
            float s = x0 + x1 + x2 + x3;
            #pragma unroll
            for (int off = 16; off > 0; off >>= 1)
                s += __shfl_xor_sync(0xffffffffu, s, off);
            float mu = s * (1.0f / 128.0f);
            float d0 = x0 - mu, d1 = x1 - mu, d2 = x2 - mu, d3 = x3 - mu;
            float q = d0 * d0 + d1 * d1 + d2 * d2 + d3 * d3;
            #pragma unroll
            for (int off = 16; off > 0; off >>= 1)
                q += __shfl_xor_sync(0xffffffffu, q, off);
            float rstd = rsqrtf(q * (1.0f / 128.0f) + LN_EPS);
            float m = sm[MF_OFF + v];
            long long base = (nbase + v) * D;
            out[base + lane]      = (d0 * rstd * g0 + b0) * m;
            out[base + lane + 32] = (d1 * rstd * g1 + b1) * m;
            out[base + lane + 64] = (d2 * rstd * g2 + b2) * m;
            out[base + lane + 96] = (d3 * rstd * g3 + b3) * m;
        }
    }
}

extern "C" void kernel_launch(void* const* d_in, const int* in_sizes, int n_in,
                              void* d_out, int out_size) {
    using namespace cfg;
    const float* h = (const float*)d_in[0];
    const float* xy = (const float*)d_in[1];
    const void* jmask = d_in[2];
    const void* edge = d_in[3];
    const float* ew1 = (const float*)d_in[4];
    const float* eb1 = (const float*)d_in[5];
    const float* ew2 = (const float*)d_in[6];
    const float* eb2 = (const float*)d_in[7];
    const float* nw1 = (const float*)d_in[8];
    const float* nb1 = (const float*)d_in[9];
    const float* nw2 = (const float*)d_in[10];
    const float* nb2 = (const float*)d_in[11];
    const float* gamma = (const float*)d_in[12];
    const float* beta = (const float*)d_in[13];
    float* out = (float*)d_out;

    const int nbatch = in_sizes[0] / (V * D);

    cudaFuncSetAttribute(graph_layer_kernel,
                         cudaFuncAttributeMaxDynamicSharedMemorySize, SMEM_BYTES);
    graph_layer_kernel<<<nbatch, 256, SMEM_BYTES>>>(
        h, xy, jmask, edge, ew1, eb1, ew2, eb2,
        nw1, nb1, nw2, nb2, gamma, beta, out);
}

// round 5
// speedup vs baseline: 1.4430x; 1.2213x over previous
#include <cuda_runtime.h>

// Problem constants (fixed by the dataset)
namespace cfg {
constexpr int V = 17;      // nodes
constexpr int D = 128;     // feature dim
constexpr int H = 256;     // hidden dim
constexpr int E = 32;      // edges
constexpr float LN_EPS = 1e-5f;
constexpr int PAD = 20;    // padded row (floats), 80B => 16B-aligned rows

// ---- shared-memory layout (float offsets) ----
constexpr int HT_OFF  = 0;                   // hT[128][20], live A..E
constexpr int R3_OFF  = HT_OFF + D * PAD;    // hsumT[256][20] (C..C2), then hid2T[256][20] (D..E)
constexpr int HST_OFF = R3_OFF;
constexpr int H2T_OFF = R3_OFF;
constexpr int R2_OFF  = R3_OFF + H * PAD;    // P+Q (B..C), then AG+RED+XB
constexpr int P_OFF   = R2_OFF;              // P[17][256]
constexpr int Q_OFF   = R2_OFF + V * H;      // Q[17][256]
constexpr int AG_OFF  = R2_OFF;              // aggT[128][20] (C2..D)
constexpr int RED_OFF = R2_OFF + D * PAD;    // partials [256][17] (D)
constexpr int XB_OFF  = RED_OFF + H * V;     // x[17][128] (E..F)
constexpr int R2_END  = XB_OFF + V * D;
// C2 split-K partials: 3*128*17 = 6528 floats in RED+XB (dead during C2)
constexpr int C2P_OFF = RED_OFF;
// E split-K partials: 6528 floats in AG+RED (dead during E); XB untouched
constexpr int EP_OFF  = AG_OFF;

constexpr int SX_OFF = R2_END;          // xy.x [17]
constexpr int SY_OFF = SX_OFF + V;      // xy.y [17]
constexpr int MF_OFF = SY_OFF + V;      // mask float [17]
constexpr int IV_OFF = MF_OFF + V;      // 1/max(denom,1) [17]
constexpr int HB_OFF = IV_OFF + V;      // has_neighbors [17]
constexpr int DN_OFF = HB_OFF + V;      // denom [17]
constexpr int RX_OFF = DN_OFF + V;      // rel x [32]
constexpr int RY_OFF = RX_OFF + E;      // rel y [32]
constexpr int VA_OFF = RY_OFF + E;      // edge_valid [32]
constexpr int SRX_OFF = VA_OFF + E;     // sorted rel x [32]
constexpr int SRY_OFF = SRX_OFF + E;    // sorted rel y [32]
constexpr int SVA_OFF = SRY_OFF + E;    // sorted valid [32]
constexpr int INT_OFF = SVA_OFF + E;    // int region
// ints: dst[32] src[32] ssrc[32] eord[32] cnt[17] off[18]
constexpr int I_DST = 0, I_SRC = 32, I_SSRC = 64, I_EORD = 96, I_CNT = 128, I_OFFA = 145;
constexpr int SMEM_FLOATS = INT_OFF + 163 + 13;  // pad
constexpr int SMEM_BYTES = SMEM_FLOATS * 4;
}  // namespace cfg

typedef unsigned long long u64;

// ---- packed fp32x2 helpers (sm_103a FFMA2 path; ptxas never emits this) ----
__device__ __forceinline__ u64 pk2(float x) {
    u64 r; asm("mov.b64 %0, {%1, %1};" : "=l"(r) : "f"(x)); return r;
}
__device__ __forceinline__ void fma2(u64& d, u64 a, u64 b) {
    asm("fma.rn.f32x2 %0, %1, %2, %0;" : "+l"(d) : "l"(a), "l"(b));
}
__device__ __forceinline__ float2 up2(u64 v) {
    float2 r; asm("mov.b64 {%0, %1}, %2;" : "=f"(r.x), "=f"(r.y) : "l"(v)); return r;
}

struct A17 { u64 p[8]; float s; };
__device__ __forceinline__ A17 load17p(const float* __restrict__ p) {
    // 16B-aligned rows: 4x LDS.128 (as u64 pairs) + 1 scalar
    A17 a;
    ulonglong2 t0 = *reinterpret_cast<const ulonglong2*>(p);
    ulonglong2 t1 = *reinterpret_cast<const ulonglong2*>(p + 4);
    ulonglong2 t2 = *reinterpret_cast<const ulonglong2*>(p + 8);
    ulonglong2 t3 = *reinterpret_cast<const ulonglong2*>(p + 12);
    a.p[0] = t0.x; a.p[1] = t0.y; a.p[2] = t1.x; a.p[3] = t1.y;
    a.p[4] = t2.x; a.p[5] = t2.y; a.p[6] = t3.x; a.p[7] = t3.y;
    a.s = p[16];
    return a;
}
__device__ __forceinline__ void unpack17(const u64* acc, float accs, float* v) {
    #pragma unroll
    for (int i = 0; i < 8; i++) {
        float2 f = up2(acc[i]);
        v[2 * i] = f.x; v[2 * i + 1] = f.y;
    }
    v[16] = accs;
}

__global__ __launch_bounds__(256, 3) void graph_layer_kernel(
    const float* __restrict__ h, const float* __restrict__ xy,
    const void* __restrict__ jmask_raw, const void* __restrict__ edge_raw,
    const float* __restrict__ ew1, const float* __restrict__ eb1,
    const float* __restrict__ ew2, const float* __restrict__ eb2,
    const float* __restrict__ nw1, const float* __restrict__ nb1,
    const float* __restrict__ nw2, const float* __restrict__ nb2,
    const float* __restrict__ gamma, const float* __restrict__ beta,
    float* __restrict__ out)
{
    using namespace cfg;
    extern __shared__ float sm[];
    int* smi = reinterpret_cast<int*>(sm + INT_OFF);
    __shared__ int s_etype;  // 0 = int32, 1 = int64
    __shared__ int s_mtype;  // 0 = bool(u8), 1 = int32, 2 = float32

    const int n = blockIdx.x;
    const int tid = threadIdx.x;
    const long long nbase = (long long)n * V;

    // ---------------- Phase A0: dtype self-detection ----------------
    if (tid == 0) {
        const unsigned* ew = (const unsigned*)edge_raw;
        unsigned odd_or = 0;
        #pragma unroll
        for (int i = 1; i < 2 * E; i += 2) odd_or |= ew[i];
        s_etype = (odd_or == 0) ? 1 : 0;
        const unsigned* mw = (const unsigned*)jmask_raw;
        bool all_i = true, all_f = true;
        #pragma unroll
        for (int i = 0; i < 64; i++) {
            unsigned w = mw[i];
            all_i = all_i && (w <= 1u);
            all_f = all_f && (w == 0u || w == 0x3F800000u);
        }
        s_mtype = all_i ? 1 : (all_f ? 2 : 0);
    }
    // h transpose load (vectorized)
    {
        const float4* h4 = reinterpret_cast<const float4*>(h + nbase * D);
        for (int idx = tid; idx < V * D / 4; idx += 256) {
            int v = (idx * 4) / D, k4 = (idx * 4) % D;
            float4 t = h4[idx];
            sm[HT_OFF + (k4 + 0) * PAD + v] = t.x;
            sm[HT_OFF + (k4 + 1) * PAD + v] = t.y;
            sm[HT_OFF + (k4 + 2) * PAD + v] = t.z;
            sm[HT_OFF + (k4 + 3) * PAD + v] = t.w;
        }
    }
    if (tid < V) {
        sm[SX_OFF + tid] = xy[(nbase + tid) * 2 + 0];
        sm[SY_OFF + tid] = xy[(nbase + tid) * 2 + 1];
    }
    __syncthreads();

    if (tid < V) {
        float mf;
        if (s_mtype == 0)
            mf = ((const unsigned char*)jmask_raw)[nbase + tid] ? 1.0f : 0.0f;
        else if (s_mtype == 1)
            mf = ((const int*)jmask_raw)[nbase + tid] ? 1.0f : 0.0f;
        else
            mf = (((const float*)jmask_raw)[nbase + tid] != 0.0f) ? 1.0f : 0.0f;
        sm[MF_OFF + tid] = mf;
    }
    if (tid < E) {
        int dv, sv;
        if (s_etype == 1) {
            const long long* e64 = (const long long*)edge_raw;
            dv = (int)e64[tid * 2 + 0];
            sv = (int)e64[tid * 2 + 1];
        } else {
            const int* e32 = (const int*)edge_raw;
            dv = e32[tid * 2 + 0];
            sv = e32[tid * 2 + 1];
        }
        smi[I_DST + tid] = dv;
        smi[I_SRC + tid] = sv;
    }
    __syncthreads();

    if (tid < E) {
        int dv = smi[I_DST + tid], sv = smi[I_SRC + tid];
        sm[RX_OFF + tid] = sm[SX_OFF + sv] - sm[SX_OFF + dv];
        sm[RY_OFF + tid] = sm[SY_OFF + sv] - sm[SY_OFF + dv];
        sm[VA_OFF + tid] = sm[MF_OFF + dv] * sm[MF_OFF + sv];
    }
    if (tid >= 64 && tid < 64 + V) {
        int v = tid - 64, c = 0;
        #pragma unroll
        for (int e = 0; e < E; e++) c += (smi[I_DST + e] == v);
        smi[I_CNT + v] = c;
    }
    __syncthreads();

    if (tid == 0) {
        int o = 0;
        #pragma unroll
        for (int v = 0; v < V; v++) { smi[I_OFFA + v] = o; o += smi[I_CNT + v]; }
        smi[I_OFFA + V] = o;
    }
    __syncthreads();

    if (tid < V) {
        int pos = smi[I_OFFA + tid];
        float dn = 0.0f;
        #pragma unroll
        for (int e = 0; e < E; e++) {
            if (smi[I_DST + e] == tid) {
                smi[I_EORD + pos++] = e;
                dn += sm[VA_OFF + e];
            }
        }
        sm[DN_OFF + tid] = dn;
        sm[IV_OFF + tid] = 1.0f / fmaxf(dn, 1.0f);
        sm[HB_OFF + tid] = dn > 0.0f ? 1.0f : 0.0f;
    }
    __syncthreads();

    if (tid < E) {
        int e = smi[I_EORD + tid];
        smi[I_SSRC + tid] = smi[I_SRC + e];
        sm[SRX_OFF + tid] = sm[RX_OFF + e];
        sm[SRY_OFF + tid] = sm[RY_OFF + e];
        sm[SVA_OFF + tid] = sm[VA_OFF + e];
    }
    __syncthreads();

    // ------- Phase B: P = h @ ew1[0:128], Q = h @ ew1[128:256], 2 cols/thread, packed -------
    {
        const int c = tid * 2;
        const float* wp = (c < H) ? (ew1 + c) : (ew1 + D * H + (c - H));
        u64 acc0[8] = {}, acc1[8] = {};
        float acc0s = 0.f, acc1s = 0.f;
        #pragma unroll 2
        for (int k = 0; k < D; k++) {
            A17 a = load17p(sm + HT_OFF + k * PAD);
            float2 w = *reinterpret_cast<const float2*>(wp + (long long)k * H);
            u64 w0 = pk2(w.x), w1 = pk2(w.y);
            #pragma unroll
            for (int i = 0; i < 8; i++) {
                fma2(acc0[i], a.p[i], w0);
                fma2(acc1[i], a.p[i], w1);
            }
            acc0s = fmaf(a.s, w.x, acc0s);
            acc1s = fmaf(a.s, w.y, acc1s);
        }
        float* dbuf = (c < H) ? (sm + P_OFF) : (sm + Q_OFF);
        const int cc = c & (H - 1);
        #pragma unroll
        for (int i = 0; i < 8; i++) {
            float2 f0 = up2(acc0[i]), f1 = up2(acc1[i]);
            dbuf[(2 * i)     * H + cc]     = f0.x;
            dbuf[(2 * i)     * H + cc + 1] = f1.x;
            dbuf[(2 * i + 1) * H + cc]     = f0.y;
            dbuf[(2 * i + 1) * H + cc + 1] = f1.y;
        }
        dbuf[16 * H + cc]     = acc0s;
        dbuf[16 * H + cc + 1] = acc1s;
    }
    __syncthreads();

    // ------- Phase C: hsumT[j][v] = sum over edges of dst v (sorted lists) -------
    {
        const int j = tid;
        const float b1v = eb1[j];
        const float wx = ew1[(2 * D) * H + j];
        const float wy = ew1[(2 * D + 1) * H + j];
        int o0 = smi[I_OFFA + 0];
        #pragma unroll 1
        for (int v = 0; v < V; v++) {
            const int o1 = smi[I_OFFA + v + 1];
            const float pv = sm[P_OFF + v * H + j];
            float acc = 0.0f;
            for (int i = o0; i < o1; i++) {
                const int sv = smi[I_SSRC + i];
                float hid = pv + sm[Q_OFF + sv * H + j]
                          + sm[SRX_OFF + i] * wx + sm[SRY_OFF + i] * wy + b1v;
                acc = fmaf(fmaxf(hid, 0.0f), sm[SVA_OFF + i], acc);
            }
            sm[HST_OFF + j * PAD + v] = acc;
            o0 = o1;
        }
    }
    __syncthreads();

    // ------- Phase C2: agg = (hsumT^T @ ew2 + denom*eb2) / max(denom,1), cpt=2, split-K 4 -------
    {
        const int g = tid & 63;          // col pair: c0 = 2g
        const int kh = tid >> 6;         // k-quarter 0..3
        const int c0 = g * 2;
        u64 acc0[8] = {}, acc1[8] = {};
        float acc0s = 0.f, acc1s = 0.f;
        const float* hb = sm + HST_OFF + kh * 64 * PAD;
        const float* w = ew2 + (long long)(kh * 64) * D + c0;
        #pragma unroll 2
        for (int k = 0; k < 64; k++) {
            A17 a = load17p(hb + k * PAD);
            float2 wv = *reinterpret_cast<const float2*>(w + (long long)k * D);
            u64 w0 = pk2(wv.x), w1 = pk2(wv.y);
            #pragma unroll
            for (int i = 0; i < 8; i++) {
                fma2(acc0[i], a.p[i], w0);
                fma2(acc1[i], a.p[i], w1);
            }
            acc0s = fmaf(a.s, wv.x, acc0s);
            acc1s = fmaf(a.s, wv.y, acc1s);
        }
        float v0[17], v1[17];
        unpack17(acc0, acc0s, v0);
        unpack17(acc1, acc1s, v1);
        if (kh) {
            float* pp = sm + C2P_OFF + ((kh - 1) * 128 + c0) * V;
            #pragma unroll
            for (int v = 0; v < V; v++) { pp[v] = v0[v]; pp[V + v] = v1[v]; }
        }
        __syncthreads();
        if (!kh) {
            const float* p0 = sm + C2P_OFF + c0 * V;
            const float* p1 = p0 + 128 * V;
            const float* p2 = p1 + 128 * V;
            const float b20 = eb2[c0], b21 = eb2[c0 + 1];
            #pragma unroll
            for (int v = 0; v < V; v++) {
                float iv = sm[IV_OFF + v], dnb = sm[DN_OFF + v];
                float s0 = v0[v] + p0[v] + p1[v] + p2[v] + dnb * b20;
                float s1 = v1[v] + p0[V + v] + p1[V + v] + p2[V + v] + dnb * b21;
                sm[AG_OFF + c0 * PAD + v]       = s0 * iv;
                sm[AG_OFF + (c0 + 1) * PAD + v] = s1 * iv;
            }
        }
    }
    __syncthreads();

    // ------- Phase D: hid2 = relu([h, agg] @ nw1 + nb1), 2 cols/thread, split-K by source, packed -------
    {
        const int c = (tid & 127) * 2;
        const int kh = tid >> 7;          // kh=0: h rows 0..127; kh=1: agg rows 128..255
        u64 acc0[8] = {}, acc1[8] = {};
        float acc0s = 0.f, acc1s = 0.f;
        const float* ab = sm + (kh ? AG_OFF : HT_OFF);
        const float* w = nw1 + (long long)(kh * 128) * H + c;
        #pragma unroll 2
        for (int k = 0; k < 128; k++) {
            A17 a = load17p(ab + k * PAD);
            float2 wv = *reinterpret_cast<const float2*>(w + (long long)k * H);
            u64 w0 = pk2(wv.x), w1 = pk2(wv.y);
            #pragma unroll
            for (int i = 0; i < 8; i++) {
                fma2(acc0[i], a.p[i], w0);
                fma2(acc1[i], a.p[i], w1);
            }
            acc0s = fmaf(a.s, wv.x, acc0s);
            acc1s = fmaf(a.s, wv.y, acc1s);
        }
        float v0[17], v1[17];
        unpack17(acc0, acc0s, v0);
        unpack17(acc1, acc1s, v1);
        if (kh) {
            #pragma unroll
            for (int v = 0; v < V; v++) {
                sm[RED_OFF + c * V + v]       = v0[v];
                sm[RED_OFF + (c + 1) * V + v] = v1[v];
            }
        }
        __syncthreads();
        if (!kh) {
            const float bb0 = nb1[c], bb1 = nb1[c + 1];
            #pragma unroll
            for (int v = 0; v < V; v++) {
                float h0 = fmaxf(v0[v] + sm[RED_OFF + c * V + v] + bb0, 0.0f);
                float h1 = fmaxf(v1[v] + sm[RED_OFF + (c + 1) * V + v] + bb1, 0.0f);
                sm[H2T_OFF + c * PAD + v]       = h0;
                sm[H2T_OFF + (c + 1) * PAD + v] = h1;
            }
        }
    }
    __syncthreads();

    // ------- Phase E: delta = hid2 @ nw2 + nb2 ; x = h + delta*has, cpt=2, split-K 4 -------
    {
        const int g = tid & 63;
        const int kh = tid >> 6;
        const int c0 = g * 2;
        u64 acc0[8] = {}, acc1[8] = {};
        float acc0s = 0.f, acc1s = 0.f;
        const float* hb = sm + H2T_OFF + kh * 64 * PAD;
        const float* w = nw2 + (long long)(kh * 64) * D + c0;
        #pragma unroll 2
        for (int k = 0; k < 64; k++) {
            A17 a = load17p(hb + k * PAD);
            float2 wv = *reinterpret_cast<const float2*>(w + (long long)k * D);
            u64 w0 = pk2(wv.x), w1 = pk2(wv.y);
            #pragma unroll
            for (int i = 0; i < 8; i++) {
                fma2(acc0[i], a.p[i], w0);
                fma2(acc1[i], a.p[i], w1);
            }
            acc0s = fmaf(a.s, wv.x, acc0s);
            acc1s = fmaf(a.s, wv.y, acc1s);
        }
        float v0[17], v1[17];
        unpack17(acc0, acc0s, v0);
        unpack17(acc1, acc1s, v1);
        if (kh) {
            float* pp = sm + EP_OFF + ((kh - 1) * 128 + c0) * V;
            #pragma unroll
            for (int v = 0; v < V; v++) { pp[v] = v0[v]; pp[V + v] = v1[v]; }
        }
        __syncthreads();
        if (!kh) {
            const float* p0 = sm + EP_OFF + c0 * V;
            const float* p1 = p0 + 128 * V;
            const float* p2 = p1 + 128 * V;
            const float b20 = nb2[c0], b21 = nb2[c0 + 1];
            #pragma unroll
            for (int v = 0; v < V; v++) {
                float hb_v = sm[HB_OFF + v];
                float d0 = v0[v] + p0[v] + p1[v] + p2[v] + b20;
                float d1 = v1[v] + p0[V + v] + p1[V + v] + p2[V + v] + b21;
                float x0 = sm[HT_OFF + c0 * PAD + v]       + d0 * hb_v;
                float x1 = sm[HT_OFF + (c0 + 1) * PAD + v] + d1 * hb_v;
                sm[XB_OFF + v * D + c0]     = x0;
                sm[XB_OFF + v * D + c0 + 1] = x1;
            }
        }
    }
    __syncthreads();

    // ------- Phase F: LayerNorm + gamma/beta + mask -------
    {
        const int wrp = tid >> 5, lane = tid & 31;
        const float g0 = gamma[lane], g1 = gamma[lane + 32],
                    g2 = gamma[lane + 64], g3 = gamma[lane + 96];
        const float b0 = beta[lane], b1 = beta[lane + 32],
                    b2 = beta[lane + 64], b3 = beta[lane + 96];
        for (int v = wrp; v < V; v += 8) {
            float x0 = sm[XB_OFF + v * D + lane];
            float x1 = sm[XB_OFF + v * D + lane + 32];
            float x2 = sm[XB_OFF + v * D + lane + 64];
            float x3 = sm[XB_OFF + v * D + lane + 96];
            float s = x0 + x1 + x2 + x3;
            #pragma unroll
            for (int off = 16; off > 0; off >>= 1)
                s += __shfl_xor_sync(0xffffffffu, s, off);
            float mu = s * (1.0f / 128.0f);
            float d0 = x0 - mu, d1 = x1 - mu, d2 = x2 - mu, d3 = x3 - mu;
            float q = d0 * d0 + d1 * d1 + d2 * d2 + d3 * d3;
            #pragma unroll
            for (int off = 16; off > 0; off >>= 1)
                q += __shfl_xor_sync(0xffffffffu, q, off);
            float rstd = rsqrtf(q * (1.0f / 128.0f) + LN_EPS);
            float m = sm[MF_OFF + v];
            long long base = (nbase + v) * D;
            out[base + lane]      = (d0 * rstd * g0 + b0) * m;
            out[base + lane + 32] = (d1 * rstd * g1 + b1) * m;
            out[base + lane + 64] = (d2 * rstd * g2 + b2) * m;
            out[base + lane + 96] = (d3 * rstd * g3 + b3) * m;
        }
    }
}

extern "C" void kernel_launch(void* const* d_in, const int* in_sizes, int n_in,
                              void* d_out, int out_size) {
    using namespace cfg;
    const float* h = (const float*)d_in[0];
    const float* xy = (const float*)d_in[1];
    const void* jmask = d_in[2];
    const void* edge = d_in[3];
    const float* ew1 = (const float*)d_in[4];
    const float* eb1 = (const float*)d_in[5];
    const float* ew2 = (const float*)d_in[6];
    const float* eb2 = (const float*)d_in[7];
    const float* nw1 = (const float*)d_in[8];
    const float* nb1 = (const float*)d_in[9];
    const float* nw2 = (const float*)d_in[10];
    const float* nb2 = (const float*)d_in[11];
    const float* gamma = (const float*)d_in[12];
    const float* beta = (const float*)d_in[13];
    float* out = (float*)d_out;

    const int nbatch = in_sizes[0] / (V * D);

    cudaFuncSetAttribute(graph_layer_kernel,
                         cudaFuncAttributeMaxDynamicSharedMemorySize, SMEM_BYTES);
    graph_layer_kernel<<<nbatch, 256, SMEM_BYTES>>>(
        h, xy, jmask, edge, ew1, eb1, ew2, eb2,
        nw1, nb1, nw2, nb2, gamma, beta, out);
}

// round 6
// speedup vs baseline: 1.4463x; 1.0023x over previous
#include <cuda_runtime.h>

// Problem constants (fixed by the dataset)
namespace cfg {
constexpr int V = 17;      // nodes
constexpr int D = 128;     // feature dim
constexpr int H = 256;     // hidden dim
constexpr int E = 32;      // edges
constexpr float LN_EPS = 1e-5f;
constexpr int PAD = 20;    // padded row (floats), 80B => 16B-aligned rows

// ---- shared-memory layout (float offsets) ----
constexpr int HT_OFF  = 0;                   // hT[128][20], live A..E
constexpr int R3_OFF  = HT_OFF + D * PAD;    // hsumT[256][20] (C..C2), then hid2T[256][20] (D..E)
constexpr int HST_OFF = R3_OFF;
constexpr int H2T_OFF = R3_OFF;
constexpr int R2_OFF  = R3_OFF + H * PAD;    // P+Q (B..C), then AG+RED+XB
constexpr int P_OFF   = R2_OFF;              // P[17][256]
constexpr int Q_OFF   = R2_OFF + V * H;      // Q[17][256]
constexpr int AG_OFF  = R2_OFF;              // aggT[128][20] (C2..D)
constexpr int RED_OFF = R2_OFF + D * PAD;    // partials [256][17] (D)
constexpr int XB_OFF  = RED_OFF + H * V;     // x[17][128] (E..F)
constexpr int R2_END  = XB_OFF + V * D;
// C2 split-K partials: 3*128*17 = 6528 floats in RED+XB (dead during C2)
constexpr int C2P_OFF = RED_OFF;
// E split-K partials: 6528 floats in AG+RED (dead during E); XB untouched
constexpr int EP_OFF  = AG_OFF;

constexpr int SX_OFF = R2_END;          // xy.x [17]
constexpr int SY_OFF = SX_OFF + V;      // xy.y [17]
constexpr int MF_OFF = SY_OFF + V;      // mask float [17]
constexpr int IV_OFF = MF_OFF + V;      // 1/max(denom,1) [17]
constexpr int HB_OFF = IV_OFF + V;      // has_neighbors [17]
constexpr int DN_OFF = HB_OFF + V;      // denom [17]
constexpr int RX_OFF = DN_OFF + V;      // rel x [32]
constexpr int RY_OFF = RX_OFF + E;      // rel y [32]
constexpr int VA_OFF = RY_OFF + E;      // edge_valid [32]
constexpr int SRX_OFF = VA_OFF + E;     // sorted rel x [32]
constexpr int SRY_OFF = SRX_OFF + E;    // sorted rel y [32]
constexpr int SVA_OFF = SRY_OFF + E;    // sorted valid [32]
constexpr int INT_OFF = SVA_OFF + E;    // int region
// ints: dst[32] src[32] ssrc[32] eord[32] cnt[17] off[18]
constexpr int I_DST = 0, I_SRC = 32, I_SSRC = 64, I_EORD = 96, I_CNT = 128, I_OFFA = 145;
constexpr int SMEM_FLOATS = INT_OFF + 163 + 13;  // pad
constexpr int SMEM_BYTES = SMEM_FLOATS * 4;
}  // namespace cfg

typedef unsigned long long u64;

// ---- packed fp32x2 helpers (sm_103a FFMA2 path; ptxas never emits this) ----
__device__ __forceinline__ u64 pk2(float x) {
    u64 r; asm("mov.b64 %0, {%1, %1};" : "=l"(r) : "f"(x)); return r;
}
__device__ __forceinline__ void fma2(u64& d, u64 a, u64 b) {
    asm("fma.rn.f32x2 %0, %1, %2, %0;" : "+l"(d) : "l"(a), "l"(b));
}
__device__ __forceinline__ float2 up2(u64 v) {
    float2 r; asm("mov.b64 {%0, %1}, %2;" : "=f"(r.x), "=f"(r.y) : "l"(v)); return r;
}

// Per-thread GEMM tile state: 4 cols x (8 packed rows + 1 scalar row).
// rg selects rows 0-7 (rg=0) or rows 8-16 (rg=1, scalar = row 16).
struct Tile4 {
    u64 acc[4][4];
    float accs[4];
    __device__ __forceinline__ void zero() {
        #pragma unroll
        for (int c = 0; c < 4; c++) {
            #pragma unroll
            for (int j = 0; j < 4; j++) acc[c][j] = 0ull;
            accs[c] = 0.0f;
        }
    }
    // ab points at (row base rg*8) within a PAD-row; w = 4 consecutive col weights
    __device__ __forceinline__ void step(const float* __restrict__ p, float4 w) {
        ulonglong2 t0 = *reinterpret_cast<const ulonglong2*>(p);
        ulonglong2 t1 = *reinterpret_cast<const ulonglong2*>(p + 4);
        float as = p[8];   // row 16 for rg1; garbage (row 8) for rg0, never stored
        u64 a0 = t0.x, a1 = t0.y, a2 = t1.x, a3 = t1.y;
        u64 w0 = pk2(w.x), w1 = pk2(w.y), w2 = pk2(w.z), w3 = pk2(w.w);
        fma2(acc[0][0], a0, w0); fma2(acc[0][1], a1, w0);
        fma2(acc[0][2], a2, w0); fma2(acc[0][3], a3, w0);
        fma2(acc[1][0], a0, w1); fma2(acc[1][1], a1, w1);
        fma2(acc[1][2], a2, w1); fma2(acc[1][3], a3, w1);
        fma2(acc[2][0], a0, w2); fma2(acc[2][1], a1, w2);
        fma2(acc[2][2], a2, w2); fma2(acc[2][3], a3, w2);
        fma2(acc[3][0], a0, w3); fma2(acc[3][1], a1, w3);
        fma2(acc[3][2], a2, w3); fma2(acc[3][3], a3, w3);
        accs[0] = fmaf(as, w.x, accs[0]);
        accs[1] = fmaf(as, w.y, accs[1]);
        accs[2] = fmaf(as, w.z, accs[2]);
        accs[3] = fmaf(as, w.w, accs[3]);
    }
    // extract value for (col cidx, local row r: 0..8) ; r==8 only valid for rg1
    __device__ __forceinline__ float get(int cidx, int r) const {
        if (r == 8) return accs[cidx];
        float2 f = up2(acc[cidx][r >> 1]);
        return (r & 1) ? f.y : f.x;
    }
};

__global__ __launch_bounds__(256, 3) void graph_layer_kernel(
    const float* __restrict__ h, const float* __restrict__ xy,
    const void* __restrict__ jmask_raw, const void* __restrict__ edge_raw,
    const float* __restrict__ ew1, const float* __restrict__ eb1,
    const float* __restrict__ ew2, const float* __restrict__ eb2,
    const float* __restrict__ nw1, const float* __restrict__ nb1,
    const float* __restrict__ nw2, const float* __restrict__ nb2,
    const float* __restrict__ gamma, const float* __restrict__ beta,
    float* __restrict__ out)
{
    using namespace cfg;
    extern __shared__ float sm[];
    int* smi = reinterpret_cast<int*>(sm + INT_OFF);
    __shared__ int s_etype;  // 0 = int32, 1 = int64
    __shared__ int s_mtype;  // 0 = bool(u8), 1 = int32, 2 = float32

    const int n = blockIdx.x;
    const int tid = threadIdx.x;
    const long long nbase = (long long)n * V;
    const int rg = tid & 1;          // row-group: 0 -> rows 0-7, 1 -> rows 8-16
    const int r0 = rg * 8;
    const int nrows = rg ? 9 : 8;

    // ---------------- Phase A0: dtype self-detection ----------------
    if (tid == 0) {
        const unsigned* ew = (const unsigned*)edge_raw;
        unsigned odd_or = 0;
        #pragma unroll
        for (int i = 1; i < 2 * E; i += 2) odd_or |= ew[i];
        s_etype = (odd_or == 0) ? 1 : 0;
        const unsigned* mw = (const unsigned*)jmask_raw;
        bool all_i = true, all_f = true;
        #pragma unroll
        for (int i = 0; i < 64; i++) {
            unsigned w = mw[i];
            all_i = all_i && (w <= 1u);
            all_f = all_f && (w == 0u || w == 0x3F800000u);
        }
        s_mtype = all_i ? 1 : (all_f ? 2 : 0);
    }
    // h transpose load (vectorized)
    {
        const float4* h4 = reinterpret_cast<const float4*>(h + nbase * D);
        for (int idx = tid; idx < V * D / 4; idx += 256) {
            int v = (idx * 4) / D, k4 = (idx * 4) % D;
            float4 t = h4[idx];
            sm[HT_OFF + (k4 + 0) * PAD + v] = t.x;
            sm[HT_OFF + (k4 + 1) * PAD + v] = t.y;
            sm[HT_OFF + (k4 + 2) * PAD + v] = t.z;
            sm[HT_OFF + (k4 + 3) * PAD + v] = t.w;
        }
    }
    if (tid < V) {
        sm[SX_OFF + tid] = xy[(nbase + tid) * 2 + 0];
        sm[SY_OFF + tid] = xy[(nbase + tid) * 2 + 1];
    }
    __syncthreads();

    if (tid < V) {
        float mf;
        if (s_mtype == 0)
            mf = ((const unsigned char*)jmask_raw)[nbase + tid] ? 1.0f : 0.0f;
        else if (s_mtype == 1)
            mf = ((const int*)jmask_raw)[nbase + tid] ? 1.0f : 0.0f;
        else
            mf = (((const float*)jmask_raw)[nbase + tid] != 0.0f) ? 1.0f : 0.0f;
        sm[MF_OFF + tid] = mf;
    }
    if (tid < E) {
        int dv, sv;
        if (s_etype == 1) {
            const long long* e64 = (const long long*)edge_raw;
            dv = (int)e64[tid * 2 + 0];
            sv = (int)e64[tid * 2 + 1];
        } else {
            const int* e32 = (const int*)edge_raw;
            dv = e32[tid * 2 + 0];
            sv = e32[tid * 2 + 1];
        }
        smi[I_DST + tid] = dv;
        smi[I_SRC + tid] = sv;
    }
    __syncthreads();

    if (tid < E) {
        int dv = smi[I_DST + tid], sv = smi[I_SRC + tid];
        sm[RX_OFF + tid] = sm[SX_OFF + sv] - sm[SX_OFF + dv];
        sm[RY_OFF + tid] = sm[SY_OFF + sv] - sm[SY_OFF + dv];
        sm[VA_OFF + tid] = sm[MF_OFF + dv] * sm[MF_OFF + sv];
    }
    if (tid >= 64 && tid < 64 + V) {
        int v = tid - 64, c = 0;
        #pragma unroll
        for (int e = 0; e < E; e++) c += (smi[I_DST + e] == v);
        smi[I_CNT + v] = c;
    }
    __syncthreads();

    if (tid == 0) {
        int o = 0;
        #pragma unroll
        for (int v = 0; v < V; v++) { smi[I_OFFA + v] = o; o += smi[I_CNT + v]; }
        smi[I_OFFA + V] = o;
    }
    __syncthreads();

    if (tid < V) {
        int pos = smi[I_OFFA + tid];
        float dn = 0.0f;
        #pragma unroll
        for (int e = 0; e < E; e++) {
            if (smi[I_DST + e] == tid) {
                smi[I_EORD + pos++] = e;
                dn += sm[VA_OFF + e];
            }
        }
        sm[DN_OFF + tid] = dn;
        sm[IV_OFF + tid] = 1.0f / fmaxf(dn, 1.0f);
        sm[HB_OFF + tid] = dn > 0.0f ? 1.0f : 0.0f;
    }
    __syncthreads();

    if (tid < E) {
        int e = smi[I_EORD + tid];
        smi[I_SSRC + tid] = smi[I_SRC + e];
        sm[SRX_OFF + tid] = sm[RX_OFF + e];
        sm[SRY_OFF + tid] = sm[RY_OFF + e];
        sm[SVA_OFF + tid] = sm[VA_OFF + e];
    }
    __syncthreads();

    // ------- Phase B: P = h @ ew1[0:128], Q = h @ ew1[128:256] -------
    // 2 row-groups x 128 col-groups (cpt=4)
    {
        const int c = (tid >> 1) * 4;  // combined col 0..508
        const float* wp = (c < H) ? (ew1 + c) : (ew1 + D * H + (c - H));
        Tile4 t; t.zero();
        const float* ab = sm + HT_OFF + r0;
        #pragma unroll 4
        for (int k = 0; k < D; k++)
            t.step(ab + k * PAD, *reinterpret_cast<const float4*>(wp + (long long)k * H));
        float* dbuf = (c < H) ? (sm + P_OFF) : (sm + Q_OFF);
        const int cc = c & (H - 1);
        #pragma unroll
        for (int j = 0; j < 4; j++) {
            float2 f0 = up2(t.acc[0][j]), f1 = up2(t.acc[1][j]),
                   f2 = up2(t.acc[2][j]), f3 = up2(t.acc[3][j]);
            *reinterpret_cast<float4*>(&dbuf[(r0 + 2 * j) * H + cc]) =
                make_float4(f0.x, f1.x, f2.x, f3.x);
            *reinterpret_cast<float4*>(&dbuf[(r0 + 2 * j + 1) * H + cc]) =
                make_float4(f0.y, f1.y, f2.y, f3.y);
        }
        if (rg)
            *reinterpret_cast<float4*>(&dbuf[16 * H + cc]) =
                make_float4(t.accs[0], t.accs[1], t.accs[2], t.accs[3]);
    }
    __syncthreads();

    // ------- Phase C: hsumT[j][v] = sum over edges of dst v (sorted lists) -------
    {
        const int j = tid;
        const float b1v = eb1[j];
        const float wx = ew1[(2 * D) * H + j];
        const float wy = ew1[(2 * D + 1) * H + j];
        int o0 = smi[I_OFFA + 0];
        #pragma unroll 1
        for (int v = 0; v < V; v++) {
            const int o1 = smi[I_OFFA + v + 1];
            const float pv = sm[P_OFF + v * H + j];
            float acc = 0.0f;
            for (int i = o0; i < o1; i++) {
                const int sv = smi[I_SSRC + i];
                float hid = pv + sm[Q_OFF + sv * H + j]
                          + sm[SRX_OFF + i] * wx + sm[SRY_OFF + i] * wy + b1v;
                acc = fmaf(fmaxf(hid, 0.0f), sm[SVA_OFF + i], acc);
            }
            sm[HST_OFF + j * PAD + v] = acc;
            o0 = o1;
        }
    }
    __syncthreads();

    // ------- Phase C2: agg = (hsumT^T @ ew2 + denom*eb2) / max(denom,1) -------
    // 2 rg x 32 cg (cpt=4) x 4 split-K
    {
        const int cg = (tid >> 1) & 31;
        const int kh = tid >> 6;
        const int c = cg * 4;          // col 0..124
        Tile4 t; t.zero();
        const float* ab = sm + HST_OFF + (kh * 64) * PAD + r0;
        const float* wp = ew2 + (long long)(kh * 64) * D + c;
        #pragma unroll 4
        for (int k = 0; k < 64; k++)
            t.step(ab + k * PAD, *reinterpret_cast<const float4*>(wp + (long long)k * D));
        if (kh) {
            float* pp = sm + C2P_OFF + ((kh - 1) * 128 + c) * V;
            #pragma unroll
            for (int ci = 0; ci < 4; ci++)
                for (int r = 0; r < nrows; r++)
                    pp[ci * V + r0 + r] = t.get(ci, r);
        }
        __syncthreads();
        if (!kh) {
            #pragma unroll
            for (int ci = 0; ci < 4; ci++) {
                const float* pp = sm + C2P_OFF + (c + ci) * V;
                const float b2 = eb2[c + ci];
                for (int r = 0; r < nrows; r++) {
                    int v = r0 + r;
                    float a = t.get(ci, r) + pp[v] + pp[128 * V + v] + pp[256 * V + v]
                            + sm[DN_OFF + v] * b2;
                    sm[AG_OFF + (c + ci) * PAD + v] = a * sm[IV_OFF + v];
                }
            }
        }
    }
    __syncthreads();

    // ------- Phase D: hid2 = relu([h, agg] @ nw1 + nb1) -------
    // 2 rg x 64 cg (cpt=4) x 2 source-halves
    {
        const int cg = (tid >> 1) & 63;
        const int kh = tid >> 7;       // 0: h rows 0..127, 1: agg rows 128..255
        const int c = cg * 4;          // col 0..252
        Tile4 t; t.zero();
        const float* ab = sm + (kh ? AG_OFF : HT_OFF) + r0;
        const float* wp = nw1 + (long long)(kh * 128) * H + c;
        #pragma unroll 4
        for (int k = 0; k < 128; k++)
            t.step(ab + k * PAD, *reinterpret_cast<const float4*>(wp + (long long)k * H));
        if (kh) {
            float* pp = sm + RED_OFF + c * V;
            #pragma unroll
            for (int ci = 0; ci < 4; ci++)
                for (int r = 0; r < nrows; r++)
                    pp[ci * V + r0 + r] = t.get(ci, r);
        }
        __syncthreads();
        if (!kh) {
            #pragma unroll
            for (int ci = 0; ci < 4; ci++) {
                const float* pp = sm + RED_OFF + (c + ci) * V;
                const float bb = nb1[c + ci];
                for (int r = 0; r < nrows; r++) {
                    int v = r0 + r;
                    sm[H2T_OFF + (c + ci) * PAD + v] =
                        fmaxf(t.get(ci, r) + pp[v] + bb, 0.0f);
                }
            }
        }
    }
    __syncthreads();

    // ------- Phase E: delta = hid2 @ nw2 + nb2 ; x = h + delta*has -------
    // 2 rg x 32 cg (cpt=4) x 4 split-K
    {
        const int cg = (tid >> 1) & 31;
        const int kh = tid >> 6;
        const int c = cg * 4;          // col 0..124
        Tile4 t; t.zero();
        const float* ab = sm + H2T_OFF + (kh * 64) * PAD + r0;
        const float* wp = nw2 + (long long)(kh * 64) * D + c;
        #pragma unroll 4
        for (int k = 0; k < 64; k++)
            t.step(ab + k * PAD, *reinterpret_cast<const float4*>(wp + (long long)k * D));
        if (kh) {
            float* pp = sm + EP_OFF + ((kh - 1) * 128 + c) * V;
            #pragma unroll
            for (int ci = 0; ci < 4; ci++)
                for (int r = 0; r < nrows; r++)
                    pp[ci * V + r0 + r] = t.get(ci, r);
        }
        __syncthreads();
        if (!kh) {
            #pragma unroll
            for (int ci = 0; ci < 4; ci++) {
                const float* pp = sm + EP_OFF + (c + ci) * V;
                const float b2 = nb2[c + ci];
                for (int r = 0; r < nrows; r++) {
                    int v = r0 + r;
                    float delta = t.get(ci, r) + pp[v] + pp[128 * V + v] + pp[256 * V + v] + b2;
                    float xv = sm[HT_OFF + (c + ci) * PAD + v] + delta * sm[HB_OFF + v];
                    sm[XB_OFF + v * D + c + ci] = xv;
                }
            }
        }
    }
    __syncthreads();

    // ------- Phase F: LayerNorm + gamma/beta + mask -------
    {
        const int wrp = tid >> 5, lane = tid & 31;
        const float g0 = gamma[lane], g1 = gamma[lane + 32],
                    g2 = gamma[lane + 64], g3 = gamma[lane + 96];
        const float b0 = beta[lane], b1 = beta[lane + 32],
                    b2 = beta[lane + 64], b3 = beta[lane + 96];
        for (int v = wrp; v < V; v += 8) {
            float x0 = sm[XB_OFF + v * D + lane];
            float x1 = sm[XB_OFF + v * D + lane + 32];
            float x2 = sm[XB_OFF + v * D + lane + 64];
            float x3 = sm[XB_OFF + v * D + lane + 96];
            float s = x0 + x1 + x2 + x3;
            #pragma unroll
            for (int off = 16; off > 0; off >>= 1)
                s += __shfl_xor_sync(0xffffffffu, s, off);
            float mu = s * (1.0f / 128.0f);
            float d0 = x0 - mu, d1 = x1 - mu, d2 = x2 - mu, d3 = x3 - mu;
            float q = d0 * d0 + d1 * d1 + d2 * d2 + d3 * d3;
            #pragma unroll
            for (int off = 16; off > 0; off >>= 1)
                q += __shfl_xor_sync(0xffffffffu, q, off);
            float rstd = rsqrtf(q * (1.0f / 128.0f) + LN_EPS);
            float m = sm[MF_OFF + v];
            long long base = (nbase + v) * D;
            out[base + lane]      = (d0 * rstd * g0 + b0) * m;
            out[base + lane + 32] = (d1 * rstd * g1 + b1) * m;
            out[base + lane + 64] = (d2 * rstd * g2 + b2) * m;
            out[base + lane + 96] = (d3 * rstd * g3 + b3) * m;
        }
    }
}

extern "C" void kernel_launch(void* const* d_in, const int* in_sizes, int n_in,
                              void* d_out, int out_size) {
    using namespace cfg;
    const float* h = (const float*)d_in[0];
    const float* xy = (const float*)d_in[1];
    const void* jmask = d_in[2];
    const void* edge = d_in[3];
    const float* ew1 = (const float*)d_in[4];
    const float* eb1 = (const float*)d_in[5];
    const float* ew2 = (const float*)d_in[6];
    const float* eb2 = (const float*)d_in[7];
    const float* nw1 = (const float*)d_in[8];
    const float* nb1 = (const float*)d_in[9];
    const float* nw2 = (const float*)d_in[10];
    const float* nb2 = (const float*)d_in[11];
    const float* gamma = (const float*)d_in[12];
    const float* beta = (const float*)d_in[13];
    float* out = (float*)d_out;

    const int nbatch = in_sizes[0] / (V * D);

    cudaFuncSetAttribute(graph_layer_kernel,
                         cudaFuncAttributeMaxDynamicSharedMemorySize, SMEM_BYTES);
    graph_layer_kernel<<<nbatch, 256, SMEM_BYTES>>>(
        h, xy, jmask, edge, ew1, eb1, ew2, eb2,
        nw1, nb1, nw2, nb2, gamma, beta, out);
}

// round 7
// speedup vs baseline: 1.4792x; 1.0227x over previous
#include <cuda_runtime.h>

namespace cfg {
constexpr int V = 17;
constexpr int D = 128;
constexpr int H = 256;
constexpr int E = 32;
constexpr float LN_EPS = 1e-5f;
constexpr int PAD = 20;   // 80B rows, 16B-aligned

// ---- shared memory layout (float offsets) ----
constexpr int HT_OFF  = 0;                 // hT[128][20]          (A..E)
constexpr int R3_OFF  = HT_OFF + D * PAD;  // 2560: hsumT[256][20] (C..C2) / hid2T (D..E) / XB head (E..F)
constexpr int HST_OFF = R3_OFF;
constexpr int H2T_OFF = R3_OFF;
constexpr int XB_OFF  = R3_OFF;            // x[17][128] = 2176 fl (E epilogue, hid2T dead)
constexpr int R2_OFF  = R3_OFF + H * PAD;  // 7680
constexpr int Q_OFF   = R2_OFF;            // Q[17][256] = 4352    (B..C)
constexpr int AG_OFF  = R2_OFF;            // aggT[128][20] = 2560 (C2..D)
constexpr int EP_OFF  = R2_OFF;            // E partials [128][17] = 2176 (E, AG dead)
constexpr int C2P_OFF = R2_OFF + D * PAD;  // 10240: C2 partials [128][17] = 2176
constexpr int R2_END  = C2P_OFF + D * V;   // 12416

constexpr int MISC = R2_END;
constexpr int SX_OFF = MISC;
constexpr int SY_OFF = SX_OFF + V;
constexpr int MF_OFF = SY_OFF + V;
constexpr int IV_OFF = MF_OFF + V;
constexpr int HB_OFF = IV_OFF + V;
constexpr int DN_OFF = HB_OFF + V;
constexpr int RX_OFF = DN_OFF + V;
constexpr int RY_OFF = RX_OFF + E;
constexpr int VA_OFF = RY_OFF + E;
constexpr int SRX_OFF = VA_OFF + E;
constexpr int SRY_OFF = SRX_OFF + E;
constexpr int SVA_OFF = SRY_OFF + E;
constexpr int INT_OFF = SVA_OFF + E;
constexpr int I_DST = 0, I_SRC = 32, I_SSRC = 64, I_EORD = 96, I_CNT = 128, I_OFFA = 145;
constexpr int SMEM_FLOATS = INT_OFF + 163 + 13;
constexpr int SMEM_BYTES = SMEM_FLOATS * 4;   // ~51.5 KB -> 4 CTAs/SM
}  // namespace cfg

typedef unsigned long long u64;

__device__ __forceinline__ u64 pk2(float x) {
    u64 r; asm("mov.b64 %0, {%1, %1};" : "=l"(r) : "f"(x)); return r;
}
__device__ __forceinline__ void fma2(u64& d, u64 a, u64 b) {
    asm("fma.rn.f32x2 %0, %1, %2, %0;" : "+l"(d) : "l"(a), "l"(b));
}
__device__ __forceinline__ float2 up2(u64 v) {
    float2 r; asm("mov.b64 {%0, %1}, %2;" : "=f"(r.x), "=f"(r.y) : "l"(v)); return r;
}

// 2-column accumulator over NU packed row-pairs (NU=4: rows0-7; NU=5: rows8-17, last lane pad)
template<int NU>
struct Acc2 {
    u64 a[2][NU];
    __device__ __forceinline__ void zero() {
        #pragma unroll
        for (int c = 0; c < 2; c++)
            #pragma unroll
            for (int i = 0; i < NU; i++) a[c][i] = 0ull;
    }
    __device__ __forceinline__ void step(const float* __restrict__ p, float2 w) {
        u64 r[NU];
        ulonglong2 t0 = *reinterpret_cast<const ulonglong2*>(p);
        ulonglong2 t1 = *reinterpret_cast<const ulonglong2*>(p + 4);
        r[0] = t0.x; r[1] = t0.y; r[2] = t1.x; r[3] = t1.y;
        if (NU == 5) r[NU - 1] = *reinterpret_cast<const u64*>(p + 8);
        u64 w0 = pk2(w.x), w1 = pk2(w.y);
        #pragma unroll
        for (int i = 0; i < NU; i++) { fma2(a[0][i], r[i], w0); fma2(a[1][i], r[i], w1); }
    }
    __device__ __forceinline__ float get(int c, int r) const {
        float2 f = up2(a[c][r >> 1]); return (r & 1) ? f.y : f.x;
    }
};

// ---------------- templated GEMM phases (RG = warp-uniform row group) ----------------

template<int RG>
__device__ __forceinline__ void phaseC2(float* sm, int cg, int kh,
                                        const float* __restrict__ ew2,
                                        const float* __restrict__ eb2) {
    using namespace cfg;
    constexpr int NU = RG ? 5 : 4;
    const int r0 = RG * 8, nval = RG ? 9 : 8;
    const int c = cg * 2;
    Acc2<NU> t; t.zero();
    const float* ab = sm + HST_OFF + (kh * 128) * PAD + r0;
    const float* wp = ew2 + (long long)(kh * 128) * D + c;
    #pragma unroll 4
    for (int k = 0; k < 128; k++)
        t.step(ab + k * PAD, *reinterpret_cast<const float2*>(wp + (long long)k * D));
    if (kh) {
        #pragma unroll
        for (int ci = 0; ci < 2; ci++)
            #pragma unroll
            for (int r = 0; r < nval; r++)
                sm[C2P_OFF + (c + ci) * V + r0 + r] = t.get(ci, r);
    }
    __syncthreads();
    if (!kh) {
        #pragma unroll
        for (int ci = 0; ci < 2; ci++) {
            const float b2 = eb2[c + ci];
            #pragma unroll
            for (int r = 0; r < nval; r++) {
                int v = r0 + r;
                float a = t.get(ci, r) + sm[C2P_OFF + (c + ci) * V + v]
                        + sm[DN_OFF + v] * b2;
                sm[AG_OFF + (c + ci) * PAD + v] = a * sm[IV_OFF + v];
            }
        }
    }
}

template<int RG>
__device__ __forceinline__ void phaseD(float* sm, int cg,
                                       const float* __restrict__ nw1,
                                       const float* __restrict__ nb1) {
    using namespace cfg;
    constexpr int NU = RG ? 5 : 4;
    const int r0 = RG * 8, nval = RG ? 9 : 8;
    const int c = cg * 2;
    Acc2<NU> t; t.zero();
    const float* ab = sm + HT_OFF + r0;
    const float* wp = nw1 + c;
    #pragma unroll 4
    for (int k = 0; k < 128; k++)
        t.step(ab + k * PAD, *reinterpret_cast<const float2*>(wp + (long long)k * H));
    const float* ab2 = sm + AG_OFF + r0;
    const float* wp2 = nw1 + (long long)128 * H + c;
    #pragma unroll 4
    for (int k = 0; k < 128; k++)
        t.step(ab2 + k * PAD, *reinterpret_cast<const float2*>(wp2 + (long long)k * H));
    #pragma unroll
    for (int ci = 0; ci < 2; ci++) {
        const float bb = nb1[c + ci];
        #pragma unroll
        for (int r = 0; r < nval; r++)
            sm[H2T_OFF + (c + ci) * PAD + r0 + r] = fmaxf(t.get(ci, r) + bb, 0.0f);
    }
}

template<int RG>
__device__ __forceinline__ void phaseE(float* sm, int cg, int kh,
                                       const float* __restrict__ nw2,
                                       const float* __restrict__ nb2) {
    using namespace cfg;
    constexpr int NU = RG ? 5 : 4;
    const int r0 = RG * 8, nval = RG ? 9 : 8;
    const int c = cg * 2;
    Acc2<NU> t; t.zero();
    const float* ab = sm + H2T_OFF + (kh * 128) * PAD + r0;
    const float* wp = nw2 + (long long)(kh * 128) * D + c;
    #pragma unroll 4
    for (int k = 0; k < 128; k++)
        t.step(ab + k * PAD, *reinterpret_cast<const float2*>(wp + (long long)k * D));
    if (kh) {
        #pragma unroll
        for (int ci = 0; ci < 2; ci++)
            #pragma unroll
            for (int r = 0; r < nval; r++)
                sm[EP_OFF + (c + ci) * V + r0 + r] = t.get(ci, r);
    }
    __syncthreads();
    if (!kh) {
        #pragma unroll
        for (int ci = 0; ci < 2; ci++) {
            const float b2 = nb2[c + ci];
            #pragma unroll
            for (int r = 0; r < nval; r++) {
                int v = r0 + r;
                float delta = t.get(ci, r) + sm[EP_OFF + (c + ci) * V + v] + b2;
                float xv = sm[HT_OFF + (c + ci) * PAD + v] + delta * sm[HB_OFF + v];
                sm[XB_OFF + v * D + c + ci] = xv;
            }
        }
    }
}

__global__ __launch_bounds__(256, 4) void graph_layer_kernel(
    const float* __restrict__ h, const float* __restrict__ xy,
    const void* __restrict__ jmask_raw, const void* __restrict__ edge_raw,
    const float* __restrict__ ew1, const float* __restrict__ eb1,
    const float* __restrict__ ew2, const float* __restrict__ eb2,
    const float* __restrict__ nw1, const float* __restrict__ nb1,
    const float* __restrict__ nw2, const float* __restrict__ nb2,
    const float* __restrict__ gamma, const float* __restrict__ beta,
    float* __restrict__ out)
{
    using namespace cfg;
    extern __shared__ float sm[];
    int* smi = reinterpret_cast<int*>(sm + INT_OFF);
    __shared__ int s_etype;
    __shared__ int s_mtype;

    const int n = blockIdx.x;
    const int tid = threadIdx.x;
    const int wrp = tid >> 5, lane = tid & 31;
    const long long nbase = (long long)n * V;

    // ---------------- dtype self-detection ----------------
    if (tid == 0) {
        const unsigned* ew = (const unsigned*)edge_raw;
        unsigned odd_or = 0;
        #pragma unroll
        for (int i = 1; i < 2 * E; i += 2) odd_or |= ew[i];
        s_etype = (odd_or == 0) ? 1 : 0;
        const unsigned* mw = (const unsigned*)jmask_raw;
        bool all_i = true, all_f = true;
        #pragma unroll
        for (int i = 0; i < 64; i++) {
            unsigned w = mw[i];
            all_i = all_i && (w <= 1u);
            all_f = all_f && (w == 0u || w == 0x3F800000u);
        }
        s_mtype = all_i ? 1 : (all_f ? 2 : 0);
    }
    // h transpose
    {
        const float4* h4 = reinterpret_cast<const float4*>(h + nbase * D);
        for (int idx = tid; idx < V * D / 4; idx += 256) {
            int v = (idx * 4) / D, k4 = (idx * 4) % D;
            float4 t = h4[idx];
            sm[HT_OFF + (k4 + 0) * PAD + v] = t.x;
            sm[HT_OFF + (k4 + 1) * PAD + v] = t.y;
            sm[HT_OFF + (k4 + 2) * PAD + v] = t.z;
            sm[HT_OFF + (k4 + 3) * PAD + v] = t.w;
        }
    }
    if (tid < V) {
        sm[SX_OFF + tid] = xy[(nbase + tid) * 2 + 0];
        sm[SY_OFF + tid] = xy[(nbase + tid) * 2 + 1];
    }
    __syncthreads();

    if (tid < V) {
        float mf;
        if (s_mtype == 0)
            mf = ((const unsigned char*)jmask_raw)[nbase + tid] ? 1.0f : 0.0f;
        else if (s_mtype == 1)
            mf = ((const int*)jmask_raw)[nbase + tid] ? 1.0f : 0.0f;
        else
            mf = (((const float*)jmask_raw)[nbase + tid] != 0.0f) ? 1.0f : 0.0f;
        sm[MF_OFF + tid] = mf;
    }
    if (tid < E) {
        int dv, sv;
        if (s_etype == 1) {
            const long long* e64 = (const long long*)edge_raw;
            dv = (int)e64[tid * 2 + 0];
            sv = (int)e64[tid * 2 + 1];
        } else {
            const int* e32 = (const int*)edge_raw;
            dv = e32[tid * 2 + 0];
            sv = e32[tid * 2 + 1];
        }
        smi[I_DST + tid] = dv;
        smi[I_SRC + tid] = sv;
    }
    __syncthreads();

    if (tid < E) {
        int dv = smi[I_DST + tid], sv = smi[I_SRC + tid];
        sm[RX_OFF + tid] = sm[SX_OFF + sv] - sm[SX_OFF + dv];
        sm[RY_OFF + tid] = sm[SY_OFF + sv] - sm[SY_OFF + dv];
        sm[VA_OFF + tid] = sm[MF_OFF + dv] * sm[MF_OFF + sv];
    }
    if (tid >= 64 && tid < 64 + V) {
        int v = tid - 64, c = 0;
        #pragma unroll
        for (int e = 0; e < E; e++) c += (smi[I_DST + e] == v);
        smi[I_CNT + v] = c;
    }
    __syncthreads();

    if (tid == 0) {
        int o = 0;
        #pragma unroll
        for (int v = 0; v < V; v++) { smi[I_OFFA + v] = o; o += smi[I_CNT + v]; }
        smi[I_OFFA + V] = o;
    }
    __syncthreads();

    if (tid < V) {
        int pos = smi[I_OFFA + tid];
        float dn = 0.0f;
        #pragma unroll
        for (int e = 0; e < E; e++) {
            if (smi[I_DST + e] == tid) {
                smi[I_EORD + pos++] = e;
                dn += sm[VA_OFF + e];
            }
        }
        sm[DN_OFF + tid] = dn;
        sm[IV_OFF + tid] = 1.0f / fmaxf(dn, 1.0f);
        sm[HB_OFF + tid] = dn > 0.0f ? 1.0f : 0.0f;
    }
    __syncthreads();

    if (tid < E) {
        int e = smi[I_EORD + tid];
        smi[I_SSRC + tid] = smi[I_SRC + e];
        sm[SRX_OFF + tid] = sm[RX_OFF + e];
        sm[SRY_OFF + tid] = sm[RY_OFF + e];
        sm[SVA_OFF + tid] = sm[VA_OFF + e];
    }
    __syncthreads();

    // ------- Phase B+C fused: thread j owns column j of P (regs) and Q (smem) -------
    {
        const int j = tid;
        u64 accP[9], accQ[9];
        #pragma unroll
        for (int i = 0; i < 9; i++) { accP[i] = 0ull; accQ[i] = 0ull; }
        const float* wP = ew1 + j;
        const float* wQ = ew1 + (long long)D * H + j;
        #pragma unroll 2
        for (int k = 0; k < D; k++) {
            const float* row = sm + HT_OFF + k * PAD;
            float wpv = wP[(long long)k * H];
            float wqv = wQ[(long long)k * H];
            u64 w0 = pk2(wpv), w1 = pk2(wqv);
            ulonglong2 t0 = *reinterpret_cast<const ulonglong2*>(row);
            ulonglong2 t1 = *reinterpret_cast<const ulonglong2*>(row + 4);
            fma2(accP[0], t0.x, w0); fma2(accQ[0], t0.x, w1);
            fma2(accP[1], t0.y, w0); fma2(accQ[1], t0.y, w1);
            fma2(accP[2], t1.x, w0); fma2(accQ[2], t1.x, w1);
            fma2(accP[3], t1.y, w0); fma2(accQ[3], t1.y, w1);
            ulonglong2 t2 = *reinterpret_cast<const ulonglong2*>(row + 8);
            ulonglong2 t3 = *reinterpret_cast<const ulonglong2*>(row + 12);
            u64 t4 = *reinterpret_cast<const u64*>(row + 16);
            fma2(accP[4], t2.x, w0); fma2(accQ[4], t2.x, w1);
            fma2(accP[5], t2.y, w0); fma2(accQ[5], t2.y, w1);
            fma2(accP[6], t3.x, w0); fma2(accQ[6], t3.x, w1);
            fma2(accP[7], t3.y, w0); fma2(accQ[7], t3.y, w1);
            fma2(accP[8], t4,   w0); fma2(accQ[8], t4,   w1);
        }
        // Q column j -> smem (read back only by this thread in phase C)
        #pragma unroll
        for (int i = 0; i < 8; i++) {
            float2 f = up2(accQ[i]);
            sm[Q_OFF + (2 * i) * H + j] = f.x;
            sm[Q_OFF + (2 * i + 1) * H + j] = f.y;
        }
        sm[Q_OFF + 16 * H + j] = up2(accQ[8]).x;

        // ------- Phase C: hsumT[j][v], P from registers -------
        float Pv[17];
        #pragma unroll
        for (int i = 0; i < 8; i++) {
            float2 f = up2(accP[i]);
            Pv[2 * i] = f.x; Pv[2 * i + 1] = f.y;
        }
        Pv[16] = up2(accP[8]).x;

        const float b1v = eb1[j];
        const float wx = ew1[(long long)(2 * D) * H + j];
        const float wy = ew1[(long long)(2 * D + 1) * H + j];
        int o0 = smi[I_OFFA + 0];
        #pragma unroll
        for (int v = 0; v < V; v++) {
            const int o1 = smi[I_OFFA + v + 1];
            const float pv = Pv[v];
            float acc = 0.0f;
            for (int i = o0; i < o1; i++) {
                const int sv = smi[I_SSRC + i];
                float hid = pv + sm[Q_OFF + sv * H + j]
                          + sm[SRX_OFF + i] * wx + sm[SRY_OFF + i] * wy + b1v;
                acc = fmaf(fmaxf(hid, 0.0f), sm[SVA_OFF + i], acc);
            }
            sm[HST_OFF + j * PAD + v] = acc;
            o0 = o1;
        }
    }
    __syncthreads();

    // ------- Phase C2: agg (warp-uniform rg; cg 0..63; kh 0..1) -------
    {
        const int rg = wrp & 1;
        const int kh = (wrp >> 1) & 1;
        const int cg = (wrp >> 2) * 32 + lane;
        if (rg == 0) phaseC2<0>(sm, cg, kh, ew2, eb2);
        else         phaseC2<1>(sm, cg, kh, ew2, eb2);
    }
    __syncthreads();

    // ------- Phase D: hid2 (full K=256 per thread; cg 0..127) -------
    {
        const int rg = wrp & 1;
        const int cg = (wrp >> 1) * 32 + lane;
        if (rg == 0) phaseD<0>(sm, cg, nw1, nb1);
        else         phaseD<1>(sm, cg, nw1, nb1);
    }
    __syncthreads();

    // ------- Phase E: delta + residual -------
    {
        const int rg = wrp & 1;
        const int kh = (wrp >> 1) & 1;
        const int cg = (wrp >> 2) * 32 + lane;
        if (rg == 0) phaseE<0>(sm, cg, kh, nw2, nb2);
        else         phaseE<1>(sm, cg, kh, nw2, nb2);
    }
    __syncthreads();

    // ------- Phase F: LayerNorm + gamma/beta + mask -------
    {
        const float g0 = gamma[lane], g1 = gamma[lane + 32],
                    g2 = gamma[lane + 64], g3 = gamma[lane + 96];
        const float b0 = beta[lane], b1 = beta[lane + 32],
                    b2 = beta[lane + 64], b3 = beta[lane + 96];
        for (int v = wrp; v < V; v += 8) {
            float x0 = sm[XB_OFF + v * D + lane];
            float x1 = sm[XB_OFF + v * D + lane + 32];
            float x2 = sm[XB_OFF + v * D + lane + 64];
            float x3 = sm[XB_OFF + v * D + lane + 96];
            float s = x0 + x1 + x2 + x3;
            #pragma unroll
            for (int off = 16; off > 0; off >>= 1)
                s += __shfl_xor_sync(0xffffffffu, s, off);
            float mu = s * (1.0f / 128.0f);
            float d0 = x0 - mu, d1 = x1 - mu, d2 = x2 - mu, d3 = x3 - mu;
            float q = d0 * d0 + d1 * d1 + d2 * d2 + d3 * d3;
            #pragma unroll
            for (int off = 16; off > 0; off >>= 1)
                q += __shfl_xor_sync(0xffffffffu, q, off);
            float rstd = rsqrtf(q * (1.0f / 128.0f) + LN_EPS);
            float m = sm[MF_OFF + v];
            long long base = (nbase + v) * D;
            out[base + lane]      = (d0 * rstd * g0 + b0) * m;
            out[base + lane + 32] = (d1 * rstd * g1 + b1) * m;
            out[base + lane + 64] = (d2 * rstd * g2 + b2) * m;
            out[base + lane + 96] = (d3 * rstd * g3 + b3) * m;
        }
    }
}

extern "C" void kernel_launch(void* const* d_in, const int* in_sizes, int n_in,
                              void* d_out, int out_size) {
    using namespace cfg;
    const float* h = (const float*)d_in[0];
    const float* xy = (const float*)d_in[1];
    const void* jmask = d_in[2];
    const void* edge = d_in[3];
    const float* ew1 = (const float*)d_in[4];
    const float* eb1 = (const float*)d_in[5];
    const float* ew2 = (const float*)d_in[6];
    const float* eb2 = (const float*)d_in[7];
    const float* nw1 = (const float*)d_in[8];
    const float* nb1 = (const float*)d_in[9];
    const float* nw2 = (const float*)d_in[10];
    const float* nb2 = (const float*)d_in[11];
    const float* gamma = (const float*)d_in[12];
    const float* beta = (const float*)d_in[13];
    float* out = (float*)d_out;

    const int nbatch = in_sizes[0] / (V * D);

    cudaFuncSetAttribute(graph_layer_kernel,
                         cudaFuncAttributeMaxDynamicSharedMemorySize, SMEM_BYTES);
    graph_layer_kernel<<<nbatch, 256, SMEM_BYTES>>>(
        h, xy, jmask, edge, ew1, eb1, ew2, eb2,
        nw1, nb1, nw2, nb2, gamma, beta, out);
}